// round 16
// baseline (speedup 1.0000x reference)
#include <cuda_runtime.h>
#include <cuda_bf16.h>
#include <math.h>

typedef unsigned long long ull;

// ---------------- constants ----------------
#define T_LEN 512
#define B_SZ  64
#define E_DIM 256
#define H_DIM 256
#define S_ST  64
#define G4H   1024   // 4*H

// ---------------- device scratch ----------------
__device__ float g_xg[2][T_LEN][B_SZ][G4H];    // precomputed x-gates + bias (chain-step order)
__device__ float g_h[T_LEN * B_SZ][2 * H_DIM]; // BiLSTM features
__device__ float g_sc[T_LEN * B_SZ][S_ST];     // emission scores (incl b_lin)
__device__ float g_hx[16][T_LEN][8][256];      // per-step h slices (group, step, slice) 1KB each
__device__ unsigned g_fl[16][T_LEN][8];        // release flags for g_hx

// ---------------- helpers ----------------
__device__ __forceinline__ ull pk2(float x, float y) {
    ull r; asm("mov.b64 %0, {%1,%2};" : "=l"(r) : "f"(x), "f"(y)); return r;
}
__device__ __forceinline__ void upk2(ull v, float& x, float& y) {
    asm("mov.b64 {%0,%1}, %2;" : "=f"(x), "=f"(y) : "l"(v));
}
__device__ __forceinline__ ull fma2_(ull a, ull b, ull c) {
    ull d; asm("fma.rn.f32x2 %0, %1, %2, %3;" : "=l"(d) : "l"(a), "l"(b), "l"(c)); return d;
}
__device__ __forceinline__ ull add2_(ull a, ull b) {
    ull d; asm("add.rn.f32x2 %0, %1, %2;" : "=l"(d) : "l"(a), "l"(b)); return d;
}
__device__ __forceinline__ float sgm(float x) { return 1.0f / (1.0f + expf(-x)); }
__device__ __forceinline__ float tanh_(float x) { return 1.0f - 2.0f / (expf(2.0f * x) + 1.0f); }

__device__ __forceinline__ void spin_acquire(const unsigned* p) {
    unsigned f;
    while (true) {
        asm volatile("ld.acquire.gpu.global.u32 %0, [%1];" : "=r"(f) : "l"(p) : "memory");
        if (f) break;
        asm volatile("nanosleep.u32 64;");
    }
}
__device__ __forceinline__ void store_release(unsigned* p, unsigned v) {
    asm volatile("st.release.gpu.global.u32 [%0], %1;" :: "l"(p), "r"(v) : "memory");
}

// =====================================================================
// Kernel Z: zero the exchange flags (graph-replay safety).
// =====================================================================
__global__ void kZ() {
    int idx = blockIdx.x * blockDim.x + threadIdx.x;
    if (idx < 16 * T_LEN * 8)
        reinterpret_cast<unsigned*>(g_fl)[idx] = 0u;
}

// =====================================================================
// Kernel A: x-gates GEMM. Inner loop slimmed: M-pairs via direct
// ulonglong2 loads from As; N-dups pre-duplicated in SMEM (permuted
// layout p(n) = (n&3)*16 + (n>>2) for conflict-free LDS.64).
// 22 issue slots / 16 FFMA2 per k (was 27).
// =====================================================================
__global__ void __launch_bounds__(256) kA(
    const int* __restrict__ obs, const float* __restrict__ emb,
    const float* __restrict__ WihF, const float* __restrict__ WihB,
    const float* __restrict__ bihF, const float* __restrict__ bhhF,
    const float* __restrict__ bihB, const float* __restrict__ bhhB)
{
    __shared__ float As[32][132];
    __shared__ float Bs2[32][130];     // duplicated (b,b) pairs, permuted
    __shared__ int rowidx[128];

    const int tid = threadIdx.x;
    const int mBase = blockIdx.x * 128;
    const int nTile = blockIdx.y;
    const int dir = nTile >> 4;
    const int nBase = (nTile & 15) * 64;
    const float* W = dir ? WihB : WihF;

    if (tid < 128) rowidx[tid] = obs[mBase + tid];
    __syncthreads();

    const int ty = tid >> 4;
    const int tx = tid & 15;

    ull acc[4][4];
#pragma unroll
    for (int m = 0; m < 4; m++)
#pragma unroll
        for (int j = 0; j < 4; j++) acc[m][j] = 0ull;

    const int arow = tid >> 3, akq = tid & 7;
    const int bn = tid >> 2, bkq = tid & 3;
    const int bper = ((bn & 3) << 4) + (bn >> 2);   // permuted column position

    float4 pa[4], pb[2];
#pragma unroll
    for (int rr = 0; rr < 4; ++rr)
        pa[rr] = *reinterpret_cast<const float4*>(
            &emb[(size_t)rowidx[arow + rr * 32] * E_DIM + akq * 4]);
#pragma unroll
    for (int hh = 0; hh < 2; ++hh)
        pb[hh] = *reinterpret_cast<const float4*>(
            &W[(size_t)(nBase + bn) * E_DIM + bkq * 8 + hh * 4]);

    for (int kt = 0; kt < 8; ++kt) {
#pragma unroll
        for (int rr = 0; rr < 4; ++rr) {
            int r = arow + rr * 32;
            As[akq * 4 + 0][r] = pa[rr].x; As[akq * 4 + 1][r] = pa[rr].y;
            As[akq * 4 + 2][r] = pa[rr].z; As[akq * 4 + 3][r] = pa[rr].w;
        }
#pragma unroll
        for (int hh = 0; hh < 2; ++hh) {
            const int kk0 = bkq * 8 + hh * 4;
            *reinterpret_cast<ull*>(&Bs2[kk0 + 0][bper * 2]) = pk2(pb[hh].x, pb[hh].x);
            *reinterpret_cast<ull*>(&Bs2[kk0 + 1][bper * 2]) = pk2(pb[hh].y, pb[hh].y);
            *reinterpret_cast<ull*>(&Bs2[kk0 + 2][bper * 2]) = pk2(pb[hh].z, pb[hh].z);
            *reinterpret_cast<ull*>(&Bs2[kk0 + 3][bper * 2]) = pk2(pb[hh].w, pb[hh].w);
        }
        __syncthreads();

        if (kt < 7) {
            const int kn = (kt + 1) * 32;
#pragma unroll
            for (int rr = 0; rr < 4; ++rr)
                pa[rr] = *reinterpret_cast<const float4*>(
                    &emb[(size_t)rowidx[arow + rr * 32] * E_DIM + kn + akq * 4]);
#pragma unroll
            for (int hh = 0; hh < 2; ++hh)
                pb[hh] = *reinterpret_cast<const float4*>(
                    &W[(size_t)(nBase + bn) * E_DIM + kn + bkq * 8 + hh * 4]);
        }

#pragma unroll 8
        for (int k = 0; k < 32; ++k) {
            ulonglong2 a01 = *reinterpret_cast<const ulonglong2*>(&As[k][ty * 8]);
            ulonglong2 a23 = *reinterpret_cast<const ulonglong2*>(&As[k][ty * 8 + 4]);
            ull ap[4] = {a01.x, a01.y, a23.x, a23.y};
            ull bd[4];
#pragma unroll
            for (int j = 0; j < 4; ++j)
                bd[j] = *reinterpret_cast<const ull*>(&Bs2[k][(j * 16 + tx) * 2]);
#pragma unroll
            for (int m = 0; m < 4; ++m)
#pragma unroll
                for (int j = 0; j < 4; ++j)
                    acc[m][j] = fma2_(ap[m], bd[j], acc[m][j]);
        }
        __syncthreads();
    }

    const int n0 = nBase + tx * 4;
    const float* bi = dir ? bihB : bihF;
    const float* bh = dir ? bhhB : bhhF;
    float bias[4];
#pragma unroll
    for (int j = 0; j < 4; ++j) bias[j] = bi[n0 + j] + bh[n0 + j];
#pragma unroll
    for (int m = 0; m < 4; ++m) {
        float lo[4], hi[4];
#pragma unroll
        for (int j = 0; j < 4; ++j) upk2(acc[m][j], lo[j], hi[j]);
        int mg0 = mBase + ty * 8 + 2 * m;
#pragma unroll
        for (int r = 0; r < 2; ++r) {
            int mg = mg0 + r;
            int t = mg >> 6, b = mg & 63;
            int sIdx = dir ? (T_LEN - 1 - t) : t;
            const float* src = r ? hi : lo;
            float4 o = make_float4(src[0] + bias[0], src[1] + bias[1],
                                   src[2] + bias[2], src[3] + bias[3]);
            *reinterpret_cast<float4*>(&g_xg[dir][sIdx][b][n0]) = o;
        }
    }
}

// =====================================================================
// Kernel B: R15 version (best known) — unchanged.
// =====================================================================
struct SmemB {
    float hbuf[2][H_DIM][8];   // ping-pong full h [k][batch]   16384 B
    ull   gred[8 * 8 * 64];    // [slot][ksplit][rowpair]       32768 B
    float gfull[8][132];       // gates [batch][row(+pad)]       4224 B
    float hstage[256];         // new h slice [u*8+bb]           1024 B
};

__global__ void __launch_bounds__(512, 1) kB(
    const float* __restrict__ WhhF, const float* __restrict__ WhhB,
    const float* __restrict__ h0, const float* __restrict__ c0)
{
    extern __shared__ char smraw[];
    SmemB& sm = *reinterpret_cast<SmemB*>(smraw);

    const int tid = threadIdx.x;
    const int blk = blockIdx.x;
    const int cr = blk & 7;            // unit slice: units [32cr, 32cr+32)
    const int g = blk >> 3;            // group 0..15
    const int dir = g >> 3;
    const int b0 = (g & 7) * 8;        // 8 batches
    const float* Whh = dir ? WhhB : WhhF;
    const float* xg = &g_xg[dir][0][0][0];

    // ---- GEMV role ----
    const int c = tid >> 6;            // 0..7 (32-k chunk)
    const int rp = tid & 63;           // rows 2rp, 2rp+1
    const int jA = 2 * rp, jB = 2 * rp + 1;
    const int rgA = ((jA >> 5) << 8) + (cr << 5) + (jA & 31);
    const int rgB = ((jB >> 5) << 8) + (cr << 5) + (jB & 31);

    float wA[32], wB[32];
    {
        const float4* pA = reinterpret_cast<const float4*>(&Whh[(size_t)rgA * H_DIM + 32 * c]);
        const float4* pB = reinterpret_cast<const float4*>(&Whh[(size_t)rgB * H_DIM + 32 * c]);
#pragma unroll
        for (int qq = 0; qq < 8; ++qq) {
            float4 va = pA[qq], vb = pB[qq];
            wA[qq * 4 + 0] = va.x; wA[qq * 4 + 1] = va.y; wA[qq * 4 + 2] = va.z; wA[qq * 4 + 3] = va.w;
            wB[qq * 4 + 0] = vb.x; wB[qq * 4 + 1] = vb.y; wB[qq * 4 + 2] = vb.z; wB[qq * 4 + 3] = vb.w;
        }
    }

    // ---- reduce role ----
    const int slot = tid >> 6;         // 0..7 = rowparity*4 + batchpair
    const int rpo = tid & 63;
    const int jOut = 2 * rpo + (slot >> 2);
    const int mOut = slot & 3;
    const int rgOut = ((jOut >> 5) << 8) + (cr << 5) + (jOut & 31);
    const float* pXg0 = xg + ((size_t)(b0 + 2 * mOut)) * G4H + rgOut;
    const float* pXg1 = pXg0 + G4H;

    // ---- stager role (tid < 224): warp jsl handles remote slice jRem ----
    const int jsl = tid >> 5;          // 0..6
    const int jRem = jsl + (jsl >= cr ? 1 : 0);
    const int e = tid & 31;            // unit within slice

    // ---- init hbuf[0] ----
    for (int idx = tid; idx < 2048; idx += 512) {
        int k = idx >> 3, bb = idx & 7;
        sm.hbuf[0][k][bb] = h0[((size_t)dir * B_SZ + b0 + bb) * H_DIM + k];
    }

    // ---- cell role ----
    const int u = tid >> 3, bb = tid & 7;
    float c_reg = 0.f;
    if (tid < 256)
        c_reg = c0[((size_t)dir * B_SZ + b0 + bb) * H_DIM + cr * 32 + u];

    // ---- h gmem store role (tid < 64) ----
    const int sb = tid >> 3, skq = tid & 7;

    __syncthreads();

    for (int s = 0; s < T_LEN; ++s) {
        const int p = s & 1, q = p ^ 1;

        // ---- stage remote slices of h into hbuf[p] (steps > 0) ----
        if (s > 0 && tid < 224) {
            spin_acquire(&g_fl[g][s - 1][jRem]);   // all lanes: own acquire orders own loads
            const float4* src = reinterpret_cast<const float4*>(&g_hx[g][s - 1][jRem][e * 8]);
            float4 v0 = src[0], v1 = src[1];
            float4* dst = reinterpret_cast<float4*>(&sm.hbuf[p][32 * jRem + e][0]);
            dst[0] = v0; dst[1] = v1;
        }

        // prefetch xg for reduce role (independent of staging)
        const size_t sOff = (size_t)s * B_SZ * G4H;
        const float xv0 = pXg0[sOff];
        const float xv1 = pXg1[sOff];

        __syncthreads();   // barA: hbuf[p] complete

        // ---- GEMV over 32-k chunk, 8 batches, weights in regs ----
        ull aA0 = 0, aA1 = 0, aA2 = 0, aA3 = 0;
        ull aB0 = 0, aB1 = 0, aB2 = 0, aB3 = 0;
        const ulonglong2* hp2 =
            reinterpret_cast<const ulonglong2*>(&sm.hbuf[p][32 * c][0]);
#pragma unroll
        for (int k = 0; k < 32; ++k) {
            ulonglong2 hA = hp2[k * 2 + 0];
            ulonglong2 hB = hp2[k * 2 + 1];
            ull wa = pk2(wA[k], wA[k]);
            ull wb = pk2(wB[k], wB[k]);
            aA0 = fma2_(wa, hA.x, aA0); aA1 = fma2_(wa, hA.y, aA1);
            aA2 = fma2_(wa, hB.x, aA2); aA3 = fma2_(wa, hB.y, aA3);
            aB0 = fma2_(wb, hA.x, aB0); aB1 = fma2_(wb, hA.y, aB1);
            aB2 = fma2_(wb, hB.x, aB2); aB3 = fma2_(wb, hB.y, aB3);
        }
        {
            ull* gp = sm.gred;
            gp[(0 * 8 + c) * 64 + rp] = aA0;
            gp[(1 * 8 + c) * 64 + rp] = aA1;
            gp[(2 * 8 + c) * 64 + rp] = aA2;
            gp[(3 * 8 + c) * 64 + rp] = aA3;
            gp[(4 * 8 + c) * 64 + rp] = aB0;
            gp[(5 * 8 + c) * 64 + rp] = aB1;
            gp[(6 * 8 + c) * 64 + rp] = aB2;
            gp[(7 * 8 + c) * 64 + rp] = aB3;
        }
        __syncthreads();   // barB: gred ready

        // ---- reduce over 8 k-chunks, add xg, write gates ----
        {
            const ull* gp = &sm.gred[(size_t)slot * 8 * 64 + rpo];
            ull r0 = add2_(gp[0], gp[64]);
            ull r1 = add2_(gp[128], gp[192]);
            ull r2 = add2_(gp[256], gp[320]);
            ull r3 = add2_(gp[384], gp[448]);
            ull r = add2_(add2_(r0, r1), add2_(r2, r3));
            r = add2_(r, pk2(xv0, xv1));
            float lo, hi; upk2(r, lo, hi);
            sm.gfull[2 * mOut][jOut] = lo;
            sm.gfull[2 * mOut + 1][jOut] = hi;
        }
        __syncthreads();   // barC: gates ready

        // ---- LSTM cell (tid < 256): smem + direct coalesced gmem publish ----
        if (tid < 256) {
            float gi = sm.gfull[bb][u];
            float gf = sm.gfull[bb][32 + u];
            float gg = sm.gfull[bb][64 + u];
            float go = sm.gfull[bb][96 + u];
            float cc = sgm(gf) * c_reg + sgm(gi) * tanh_(gg);
            c_reg = cc;
            float hv = sgm(go) * tanh_(cc);
            sm.hstage[tid] = hv;
            sm.hbuf[q][cr * 32 + u][bb] = hv;      // own slice local
            if (s < T_LEN - 1)
                g_hx[g][s][cr][tid] = hv;          // publish (coalesced STG.32)
        }
        __syncthreads();   // barD: hstage + publish stores done

        // ---- release flag (store/sync/fence/flag pattern) ----
        if (s < T_LEN - 1 && tid == 0) {
            __threadfence();
            store_release(&g_fl[g][s][cr], 1u);
        }

        // ---- h to gmem for score GEMM (tid < 64) ----
        if (tid < 64) {
            float4 o;
            o.x = sm.hstage[(skq * 4 + 0) * 8 + sb];
            o.y = sm.hstage[(skq * 4 + 1) * 8 + sb];
            o.z = sm.hstage[(skq * 4 + 2) * 8 + sb];
            o.w = sm.hstage[(skq * 4 + 3) * 8 + sb];
            int tOut = dir ? (T_LEN - 1 - s) : s;
            *reinterpret_cast<float4*>(
                &g_h[(size_t)tOut * B_SZ + b0 + sb][dir * H_DIM + cr * 32 + skq * 4]) = o;
        }
    }
}

// =====================================================================
// Kernel S: emission scores GEMM — same slot-slimming as kA.
// =====================================================================
__global__ void __launch_bounds__(256) kS(
    const float* __restrict__ Wlin, const float* __restrict__ blin)
{
    __shared__ float As[32][132];
    __shared__ float Bs2[32][130];

    const int tid = threadIdx.x;
    const int mBase = blockIdx.x * 128;

    const int ty = tid >> 4;
    const int tx = tid & 15;

    ull acc[4][4];
#pragma unroll
    for (int m = 0; m < 4; m++)
#pragma unroll
        for (int j = 0; j < 4; j++) acc[m][j] = 0ull;

    const int arow = tid >> 3, akq = tid & 7;
    const int bn = tid >> 2, bkq = tid & 3;
    const int bper = ((bn & 3) << 4) + (bn >> 2);

    float4 pa[4], pb[2];
#pragma unroll
    for (int rr = 0; rr < 4; ++rr)
        pa[rr] = *reinterpret_cast<const float4*>(&g_h[mBase + arow + rr * 32][akq * 4]);
#pragma unroll
    for (int hh = 0; hh < 2; ++hh)
        pb[hh] = *reinterpret_cast<const float4*>(
            &Wlin[(size_t)bn * (2 * H_DIM) + bkq * 8 + hh * 4]);

    for (int kt = 0; kt < 16; ++kt) {
#pragma unroll
        for (int rr = 0; rr < 4; ++rr) {
            int r = arow + rr * 32;
            As[akq * 4 + 0][r] = pa[rr].x; As[akq * 4 + 1][r] = pa[rr].y;
            As[akq * 4 + 2][r] = pa[rr].z; As[akq * 4 + 3][r] = pa[rr].w;
        }
#pragma unroll
        for (int hh = 0; hh < 2; ++hh) {
            const int kk0 = bkq * 8 + hh * 4;
            *reinterpret_cast<ull*>(&Bs2[kk0 + 0][bper * 2]) = pk2(pb[hh].x, pb[hh].x);
            *reinterpret_cast<ull*>(&Bs2[kk0 + 1][bper * 2]) = pk2(pb[hh].y, pb[hh].y);
            *reinterpret_cast<ull*>(&Bs2[kk0 + 2][bper * 2]) = pk2(pb[hh].z, pb[hh].z);
            *reinterpret_cast<ull*>(&Bs2[kk0 + 3][bper * 2]) = pk2(pb[hh].w, pb[hh].w);
        }
        __syncthreads();

        if (kt < 15) {
            const int kn = (kt + 1) * 32;
#pragma unroll
            for (int rr = 0; rr < 4; ++rr)
                pa[rr] = *reinterpret_cast<const float4*>(
                    &g_h[mBase + arow + rr * 32][kn + akq * 4]);
#pragma unroll
            for (int hh = 0; hh < 2; ++hh)
                pb[hh] = *reinterpret_cast<const float4*>(
                    &Wlin[(size_t)bn * (2 * H_DIM) + kn + bkq * 8 + hh * 4]);
        }

#pragma unroll 8
        for (int k = 0; k < 32; ++k) {
            ulonglong2 a01 = *reinterpret_cast<const ulonglong2*>(&As[k][ty * 8]);
            ulonglong2 a23 = *reinterpret_cast<const ulonglong2*>(&As[k][ty * 8 + 4]);
            ull ap[4] = {a01.x, a01.y, a23.x, a23.y};
            ull bd[4];
#pragma unroll
            for (int j = 0; j < 4; ++j)
                bd[j] = *reinterpret_cast<const ull*>(&Bs2[k][(j * 16 + tx) * 2]);
#pragma unroll
            for (int m = 0; m < 4; ++m)
#pragma unroll
                for (int j = 0; j < 4; ++j)
                    acc[m][j] = fma2_(ap[m], bd[j], acc[m][j]);
        }
        __syncthreads();
    }

    const int n0 = tx * 4;
    float bias[4];
#pragma unroll
    for (int j = 0; j < 4; ++j) bias[j] = blin[n0 + j];
#pragma unroll
    for (int m = 0; m < 4; ++m) {
        float lo[4], hi[4];
#pragma unroll
        for (int j = 0; j < 4; ++j) upk2(acc[m][j], lo[j], hi[j]);
        int row0 = mBase + ty * 8 + 2 * m;
#pragma unroll
        for (int r = 0; r < 2; ++r) {
            const float* src = r ? hi : lo;
            float4 o = make_float4(src[0] + bias[0], src[1] + bias[1],
                                   src[2] + bias[2], src[3] + bias[3]);
            *reinterpret_cast<float4*>(&g_sc[row0 + r][n0]) = o;
        }
    }
}

// =====================================================================
// Kernel C: Viterbi DP + backtrace (R11/R15 single-batch — unchanged).
// =====================================================================
__global__ void __launch_bounds__(512) kC(
    const float* __restrict__ pw,
    const float* __restrict__ startv, const float* __restrict__ stopv,
    float* __restrict__ out)
{
    __shared__ float delta[2][64];
    __shared__ float fin[64];
    __shared__ unsigned char bp[T_LEN - 1][64];

    const int b = blockIdx.x;
    const int tid = threadIdx.x;
    const int s = tid >> 3;      // state 0..63
    const int p = tid & 7;       // part 0..7

    float Pr[8];
#pragma unroll
    for (int i = 0; i < 8; ++i) Pr[i] = pw[(p * 8 + i) * 64 + s];

    if (p == 0) delta[0][s] = startv[s] + g_sc[b][s];
    __syncthreads();

    float scA = g_sc[(size_t)1 * B_SZ + b][s];
    float scB = g_sc[(size_t)2 * B_SZ + b][s];
    for (int t = 1; t < T_LEN; ++t) {
        const int pp = (t - 1) & 1, qq = t & 1;
        float4 d0 = *reinterpret_cast<const float4*>(&delta[pp][p * 8]);
        float4 d1 = *reinterpret_cast<const float4*>(&delta[pp][p * 8 + 4]);
        float dv[8] = {d0.x, d0.y, d0.z, d0.w, d1.x, d1.y, d1.z, d1.w};

        float best = dv[0] + Pr[0];
        int bi = p * 8;
#pragma unroll
        for (int i = 1; i < 8; ++i) {
            float v = dv[i] + Pr[i];
            if (v > best) { best = v; bi = p * 8 + i; }
        }
#pragma unroll
        for (int off = 1; off < 8; off <<= 1) {
            float ov = __shfl_xor_sync(0xffffffffu, best, off);
            int oi = __shfl_xor_sync(0xffffffffu, bi, off);
            if (ov > best || (ov == best && oi < bi)) { best = ov; bi = oi; }
        }

        const float sc = scA;
        scA = scB;
        if (t + 2 < T_LEN) scB = g_sc[(size_t)(t + 2) * B_SZ + b][s];

        if (p == 0) {
            bp[t - 1][s] = (unsigned char)bi;
            delta[qq][s] = best + sc;
        }
        __syncthreads();
    }

    if (p == 0) fin[s] = delta[(T_LEN - 1) & 1][s] + stopv[s];
    __syncthreads();

    if (tid == 0) {
        float best = fin[0]; int bi0 = 0;
        for (int i = 1; i < 64; ++i) if (fin[i] > best) { best = fin[i]; bi0 = i; }
        out[b] = best;
        int st = bi0;
        out[64 + (size_t)(T_LEN - 1) * B_SZ + b] = (float)st;
        for (int tt = T_LEN - 2; tt >= 0; --tt) {
            st = bp[tt][st];
            out[64 + (size_t)tt * B_SZ + b] = (float)st;
        }
    }
}

// =====================================================================
extern "C" void kernel_launch(void* const* d_in, const int* in_sizes, int n_in,
                              void* d_out, int out_size)
{
    const int*   obs  = (const int*)  d_in[0];
    const float* h0   = (const float*)d_in[1];
    const float* c0   = (const float*)d_in[2];
    const float* emb  = (const float*)d_in[3];
    const float* WihF = (const float*)d_in[4];
    const float* WhhF = (const float*)d_in[5];
    const float* bihF = (const float*)d_in[6];
    const float* bhhF = (const float*)d_in[7];
    const float* WihB = (const float*)d_in[8];
    const float* WhhB = (const float*)d_in[9];
    const float* bihB = (const float*)d_in[10];
    const float* bhhB = (const float*)d_in[11];
    const float* Wlin = (const float*)d_in[12];
    const float* blin = (const float*)d_in[13];
    const float* pw   = (const float*)d_in[14];
    const float* stv  = (const float*)d_in[15];
    const float* spv  = (const float*)d_in[16];
    float* out = (float*)d_out;

    const int smemB = (int)sizeof(SmemB);
    cudaFuncSetAttribute(kB, cudaFuncAttributeMaxDynamicSharedMemorySize, smemB);

    kZ<<<64, 1024>>>();
    kA<<<dim3(256, 32), 256>>>(obs, emb, WihF, WihB, bihF, bhhF, bihB, bhhB);
    kB<<<128, 512, smemB>>>(WhhF, WhhB, h0, c0);
    kS<<<256, 256>>>(Wlin, blin);
    kC<<<64, 512>>>(pw, stv, spv, out);
}

// round 17
// speedup vs baseline: 1.1548x; 1.1548x over previous
#include <cuda_runtime.h>
#include <cuda_bf16.h>
#include <math.h>

typedef unsigned long long ull;

// ---------------- constants ----------------
#define T_LEN 512
#define B_SZ  64
#define E_DIM 256
#define H_DIM 256
#define S_ST  64
#define G4H   1024   // 4*H

// ---------------- device scratch ----------------
__device__ float g_xg[2][T_LEN][B_SZ][G4H];    // precomputed x-gates + bias (chain-step order)
__device__ float g_h[T_LEN * B_SZ][2 * H_DIM]; // BiLSTM features
__device__ float g_sc[T_LEN * B_SZ][S_ST];     // emission scores (incl b_lin)
__device__ float g_hx[16][T_LEN][8][256];      // per-step h slices (group, step, slice) 1KB each
__device__ unsigned g_fl[16][T_LEN][8];        // release flags for g_hx

// ---------------- helpers ----------------
__device__ __forceinline__ ull pk2(float x, float y) {
    ull r; asm("mov.b64 %0, {%1,%2};" : "=l"(r) : "f"(x), "f"(y)); return r;
}
__device__ __forceinline__ void upk2(ull v, float& x, float& y) {
    asm("mov.b64 {%0,%1}, %2;" : "=f"(x), "=f"(y) : "l"(v));
}
__device__ __forceinline__ ull fma2_(ull a, ull b, ull c) {
    ull d; asm("fma.rn.f32x2 %0, %1, %2, %3;" : "=l"(d) : "l"(a), "l"(b), "l"(c)); return d;
}
__device__ __forceinline__ ull add2_(ull a, ull b) {
    ull d; asm("add.rn.f32x2 %0, %1, %2;" : "=l"(d) : "l"(a), "l"(b)); return d;
}
__device__ __forceinline__ float sgm(float x) { return 1.0f / (1.0f + expf(-x)); }
__device__ __forceinline__ float tanh_(float x) { return 1.0f - 2.0f / (expf(2.0f * x) + 1.0f); }

__device__ __forceinline__ void spin_acquire(const unsigned* p) {
    unsigned f;
    while (true) {
        asm volatile("ld.acquire.gpu.global.u32 %0, [%1];" : "=r"(f) : "l"(p) : "memory");
        if (f) break;
        asm volatile("nanosleep.u32 64;");
    }
}
__device__ __forceinline__ void store_release(unsigned* p, unsigned v) {
    asm volatile("st.release.gpu.global.u32 [%0], %1;" :: "l"(p), "r"(v) : "memory");
}

#define NBAR(id, cnt) \
    asm volatile("bar.sync %0, %1;" :: "r"(id), "r"(cnt) : "memory")

// =====================================================================
// Kernel Z: zero the exchange flags (graph-replay safety).
// =====================================================================
__global__ void kZ() {
    int idx = blockIdx.x * blockDim.x + threadIdx.x;
    if (idx < 16 * T_LEN * 8)
        reinterpret_cast<unsigned*>(g_fl)[idx] = 0u;
}

// =====================================================================
// Kernel A: x-gates GEMM (R15 version — at measured optimum).
// =====================================================================
__global__ void __launch_bounds__(256) kA(
    const int* __restrict__ obs, const float* __restrict__ emb,
    const float* __restrict__ WihF, const float* __restrict__ WihB,
    const float* __restrict__ bihF, const float* __restrict__ bhhF,
    const float* __restrict__ bihB, const float* __restrict__ bhhB)
{
    __shared__ float As[32][132];
    __shared__ float Bs[32][68];
    __shared__ int rowidx[128];

    const int tid = threadIdx.x;
    const int mBase = blockIdx.x * 128;
    const int nTile = blockIdx.y;
    const int dir = nTile >> 4;
    const int nBase = (nTile & 15) * 64;
    const float* W = dir ? WihB : WihF;

    if (tid < 128) rowidx[tid] = obs[mBase + tid];
    __syncthreads();

    const int ty = tid >> 4;
    const int tx = tid & 15;

    ull acc[4][4];
#pragma unroll
    for (int m = 0; m < 4; m++)
#pragma unroll
        for (int j = 0; j < 4; j++) acc[m][j] = 0ull;

    const int arow = tid >> 3, akq = tid & 7;
    const int bn = tid >> 2, bkq = tid & 3;

    float4 pa[4], pb[2];
#pragma unroll
    for (int rr = 0; rr < 4; ++rr)
        pa[rr] = *reinterpret_cast<const float4*>(
            &emb[(size_t)rowidx[arow + rr * 32] * E_DIM + akq * 4]);
#pragma unroll
    for (int hh = 0; hh < 2; ++hh)
        pb[hh] = *reinterpret_cast<const float4*>(
            &W[(size_t)(nBase + bn) * E_DIM + bkq * 8 + hh * 4]);

    for (int kt = 0; kt < 8; ++kt) {
#pragma unroll
        for (int rr = 0; rr < 4; ++rr) {
            int r = arow + rr * 32;
            As[akq * 4 + 0][r] = pa[rr].x; As[akq * 4 + 1][r] = pa[rr].y;
            As[akq * 4 + 2][r] = pa[rr].z; As[akq * 4 + 3][r] = pa[rr].w;
        }
#pragma unroll
        for (int hh = 0; hh < 2; ++hh) {
            Bs[bkq * 8 + hh * 4 + 0][bn] = pb[hh].x; Bs[bkq * 8 + hh * 4 + 1][bn] = pb[hh].y;
            Bs[bkq * 8 + hh * 4 + 2][bn] = pb[hh].z; Bs[bkq * 8 + hh * 4 + 3][bn] = pb[hh].w;
        }
        __syncthreads();

        if (kt < 7) {
            const int kn = (kt + 1) * 32;
#pragma unroll
            for (int rr = 0; rr < 4; ++rr)
                pa[rr] = *reinterpret_cast<const float4*>(
                    &emb[(size_t)rowidx[arow + rr * 32] * E_DIM + kn + akq * 4]);
#pragma unroll
            for (int hh = 0; hh < 2; ++hh)
                pb[hh] = *reinterpret_cast<const float4*>(
                    &W[(size_t)(nBase + bn) * E_DIM + kn + bkq * 8 + hh * 4]);
        }

#pragma unroll 8
        for (int k = 0; k < 32; ++k) {
            float4 a0 = *reinterpret_cast<const float4*>(&As[k][ty * 8]);
            float4 a1 = *reinterpret_cast<const float4*>(&As[k][ty * 8 + 4]);
            float4 b4 = *reinterpret_cast<const float4*>(&Bs[k][tx * 4]);
            ull ap[4] = {pk2(a0.x, a0.y), pk2(a0.z, a0.w), pk2(a1.x, a1.y), pk2(a1.z, a1.w)};
            ull bd[4] = {pk2(b4.x, b4.x), pk2(b4.y, b4.y), pk2(b4.z, b4.z), pk2(b4.w, b4.w)};
#pragma unroll
            for (int m = 0; m < 4; ++m)
#pragma unroll
                for (int j = 0; j < 4; ++j)
                    acc[m][j] = fma2_(ap[m], bd[j], acc[m][j]);
        }
        __syncthreads();
    }

    const int n0 = nBase + tx * 4;
    const float* bi = dir ? bihB : bihF;
    const float* bh = dir ? bhhB : bhhF;
    float bias[4];
#pragma unroll
    for (int j = 0; j < 4; ++j) bias[j] = bi[n0 + j] + bh[n0 + j];
#pragma unroll
    for (int m = 0; m < 4; ++m) {
        float lo[4], hi[4];
#pragma unroll
        for (int j = 0; j < 4; ++j) upk2(acc[m][j], lo[j], hi[j]);
        int mg0 = mBase + ty * 8 + 2 * m;
#pragma unroll
        for (int r = 0; r < 2; ++r) {
            int mg = mg0 + r;
            int t = mg >> 6, b = mg & 63;
            int sIdx = dir ? (T_LEN - 1 - t) : t;
            const float* src = r ? hi : lo;
            float4 o = make_float4(src[0] + bias[0], src[1] + bias[1],
                                   src[2] + bias[2], src[3] + bias[3]);
            *reinterpret_cast<float4*>(&g_xg[dir][sIdx][b][n0]) = o;
        }
    }
}

// =====================================================================
// Kernel B: R15 pipeline, but PER-CHUNK staging: chunk c's 64 threads
// stage slice c themselves, sync via named barrier (1+c, 64), then
// GEMV immediately. barA removed; own chunk never waits.
// =====================================================================
struct SmemB {
    float hbuf[2][H_DIM][8];   // ping-pong full h [k][batch]   16384 B
    ull   gred[8 * 8 * 64];    // [slot][ksplit][rowpair]       32768 B
    float gfull[8][132];       // gates [batch][row(+pad)]       4224 B
    float hstage[256];         // new h slice [u*8+bb]           1024 B
};

__global__ void __launch_bounds__(512, 1) kB(
    const float* __restrict__ WhhF, const float* __restrict__ WhhB,
    const float* __restrict__ h0, const float* __restrict__ c0)
{
    extern __shared__ char smraw[];
    SmemB& sm = *reinterpret_cast<SmemB*>(smraw);

    const int tid = threadIdx.x;
    const int blk = blockIdx.x;
    const int cr = blk & 7;            // unit slice: units [32cr, 32cr+32)
    const int g = blk >> 3;            // group 0..15
    const int dir = g >> 3;
    const int b0 = (g & 7) * 8;        // 8 batches
    const float* Whh = dir ? WhhB : WhhF;
    const float* xg = &g_xg[dir][0][0][0];

    // ---- GEMV role ----
    const int c = tid >> 6;            // 0..7 (32-k chunk == staged slice)
    const int rp = tid & 63;           // rows 2rp, 2rp+1
    const int jA = 2 * rp, jB = 2 * rp + 1;
    const int rgA = ((jA >> 5) << 8) + (cr << 5) + (jA & 31);
    const int rgB = ((jB >> 5) << 8) + (cr << 5) + (jB & 31);

    float wA[32], wB[32];
    {
        const float4* pA = reinterpret_cast<const float4*>(&Whh[(size_t)rgA * H_DIM + 32 * c]);
        const float4* pB = reinterpret_cast<const float4*>(&Whh[(size_t)rgB * H_DIM + 32 * c]);
#pragma unroll
        for (int qq = 0; qq < 8; ++qq) {
            float4 va = pA[qq], vb = pB[qq];
            wA[qq * 4 + 0] = va.x; wA[qq * 4 + 1] = va.y; wA[qq * 4 + 2] = va.z; wA[qq * 4 + 3] = va.w;
            wB[qq * 4 + 0] = vb.x; wB[qq * 4 + 1] = vb.y; wB[qq * 4 + 2] = vb.z; wB[qq * 4 + 3] = vb.w;
        }
    }

    // ---- per-chunk staging addressing (thread e2 of chunk c) ----
    const int e2 = tid & 63;                      // 16B piece of slice c
    const bool doStage = (c != cr);
    const unsigned* myFlag = &g_fl[g][0][c];      // advanced by step below
    float* stDst = &sm.hbuf[0][32 * c + (e2 >> 1)][(e2 & 1) * 4];
    const size_t hbufStrideF = (size_t)H_DIM * 8; // floats between ping-pong

    // ---- reduce role ----
    const int slot = tid >> 6;         // 0..7 = rowparity*4 + batchpair
    const int rpo = tid & 63;
    const int jOut = 2 * rpo + (slot >> 2);
    const int mOut = slot & 3;
    const int rgOut = ((jOut >> 5) << 8) + (cr << 5) + (jOut & 31);
    const float* pXg0 = xg + ((size_t)(b0 + 2 * mOut)) * G4H + rgOut;
    const float* pXg1 = pXg0 + G4H;

    // ---- init hbuf[0] ----
    for (int idx = tid; idx < 2048; idx += 512) {
        int k = idx >> 3, bb = idx & 7;
        sm.hbuf[0][k][bb] = h0[((size_t)dir * B_SZ + b0 + bb) * H_DIM + k];
    }

    // ---- cell role ----
    const int u = tid >> 3, bb = tid & 7;
    float c_reg = 0.f;
    if (tid < 256)
        c_reg = c0[((size_t)dir * B_SZ + b0 + bb) * H_DIM + cr * 32 + u];

    // ---- h gmem store role (tid < 64) ----
    const int sb = tid >> 3, skq = tid & 7;

    __syncthreads();

    for (int s = 0; s < T_LEN; ++s) {
        const int p = s & 1, q = p ^ 1;

        // prefetch xg for reduce role (independent of staging)
        const size_t sOff = (size_t)s * B_SZ * G4H;
        const float xv0 = pXg0[sOff];
        const float xv1 = pXg1[sOff];

        // ---- per-chunk staging: chunk c fetches slice c (not own slice) ----
        if (s > 0 && doStage) {
            spin_acquire(myFlag + (size_t)(s - 1) * 8);
            float4 v = *reinterpret_cast<const float4*>(&g_hx[g][s - 1][c][e2 * 4]);
            *reinterpret_cast<float4*>(stDst + (size_t)p * hbufStrideF) = v;
        }
        NBAR(1 + c, 64);   // chunk-local: slice c staged, 2 warps synced

        // ---- GEMV over 32-k chunk (slice c), 8 batches, weights in regs ----
        ull aA0 = 0, aA1 = 0, aA2 = 0, aA3 = 0;
        ull aB0 = 0, aB1 = 0, aB2 = 0, aB3 = 0;
        const ulonglong2* hp2 =
            reinterpret_cast<const ulonglong2*>(&sm.hbuf[p][32 * c][0]);
#pragma unroll
        for (int k = 0; k < 32; ++k) {
            ulonglong2 hA = hp2[k * 2 + 0];
            ulonglong2 hB = hp2[k * 2 + 1];
            ull wa = pk2(wA[k], wA[k]);
            ull wb = pk2(wB[k], wB[k]);
            aA0 = fma2_(wa, hA.x, aA0); aA1 = fma2_(wa, hA.y, aA1);
            aA2 = fma2_(wa, hB.x, aA2); aA3 = fma2_(wa, hB.y, aA3);
            aB0 = fma2_(wb, hA.x, aB0); aB1 = fma2_(wb, hA.y, aB1);
            aB2 = fma2_(wb, hB.x, aB2); aB3 = fma2_(wb, hB.y, aB3);
        }
        {
            ull* gp = sm.gred;
            gp[(0 * 8 + c) * 64 + rp] = aA0;
            gp[(1 * 8 + c) * 64 + rp] = aA1;
            gp[(2 * 8 + c) * 64 + rp] = aA2;
            gp[(3 * 8 + c) * 64 + rp] = aA3;
            gp[(4 * 8 + c) * 64 + rp] = aB0;
            gp[(5 * 8 + c) * 64 + rp] = aB1;
            gp[(6 * 8 + c) * 64 + rp] = aB2;
            gp[(7 * 8 + c) * 64 + rp] = aB3;
        }
        __syncthreads();   // barB: gred ready

        // ---- reduce over 8 k-chunks, add xg, write gates ----
        {
            const ull* gp = &sm.gred[(size_t)slot * 8 * 64 + rpo];
            ull r0 = add2_(gp[0], gp[64]);
            ull r1 = add2_(gp[128], gp[192]);
            ull r2 = add2_(gp[256], gp[320]);
            ull r3 = add2_(gp[384], gp[448]);
            ull r = add2_(add2_(r0, r1), add2_(r2, r3));
            r = add2_(r, pk2(xv0, xv1));
            float lo, hi; upk2(r, lo, hi);
            sm.gfull[2 * mOut][jOut] = lo;
            sm.gfull[2 * mOut + 1][jOut] = hi;
        }
        __syncthreads();   // barC: gates ready

        // ---- LSTM cell (tid < 256): smem + direct coalesced gmem publish ----
        if (tid < 256) {
            float gi = sm.gfull[bb][u];
            float gf = sm.gfull[bb][32 + u];
            float gg = sm.gfull[bb][64 + u];
            float go = sm.gfull[bb][96 + u];
            float cc = sgm(gf) * c_reg + sgm(gi) * tanh_(gg);
            c_reg = cc;
            float hv = sgm(go) * tanh_(cc);
            sm.hstage[tid] = hv;
            sm.hbuf[q][cr * 32 + u][bb] = hv;      // own slice local
            if (s < T_LEN - 1)
                g_hx[g][s][cr][tid] = hv;          // publish (coalesced STG.32)
        }
        __syncthreads();   // barD: hstage + publish stores done

        // ---- release flag (store/sync/fence/flag pattern) ----
        if (s < T_LEN - 1 && tid == 0) {
            __threadfence();
            store_release(&g_fl[g][s][cr], 1u);
        }

        // ---- h to gmem for score GEMM (tid < 64) ----
        if (tid < 64) {
            float4 o;
            o.x = sm.hstage[(skq * 4 + 0) * 8 + sb];
            o.y = sm.hstage[(skq * 4 + 1) * 8 + sb];
            o.z = sm.hstage[(skq * 4 + 2) * 8 + sb];
            o.w = sm.hstage[(skq * 4 + 3) * 8 + sb];
            int tOut = dir ? (T_LEN - 1 - s) : s;
            *reinterpret_cast<float4*>(
                &g_h[(size_t)tOut * B_SZ + b0 + sb][dir * H_DIM + cr * 32 + skq * 4]) = o;
        }
    }
}

// =====================================================================
// Kernel S: emission scores GEMM (R15 version).
// =====================================================================
__global__ void __launch_bounds__(256) kS(
    const float* __restrict__ Wlin, const float* __restrict__ blin)
{
    __shared__ float As[32][132];
    __shared__ float Bs[32][68];

    const int tid = threadIdx.x;
    const int mBase = blockIdx.x * 128;

    const int ty = tid >> 4;
    const int tx = tid & 15;

    ull acc[4][4];
#pragma unroll
    for (int m = 0; m < 4; m++)
#pragma unroll
        for (int j = 0; j < 4; j++) acc[m][j] = 0ull;

    const int arow = tid >> 3, akq = tid & 7;
    const int bn = tid >> 2, bkq = tid & 3;

    float4 pa[4], pb[2];
#pragma unroll
    for (int rr = 0; rr < 4; ++rr)
        pa[rr] = *reinterpret_cast<const float4*>(&g_h[mBase + arow + rr * 32][akq * 4]);
#pragma unroll
    for (int hh = 0; hh < 2; ++hh)
        pb[hh] = *reinterpret_cast<const float4*>(
            &Wlin[(size_t)bn * (2 * H_DIM) + bkq * 8 + hh * 4]);

    for (int kt = 0; kt < 16; ++kt) {
#pragma unroll
        for (int rr = 0; rr < 4; ++rr) {
            int r = arow + rr * 32;
            As[akq * 4 + 0][r] = pa[rr].x; As[akq * 4 + 1][r] = pa[rr].y;
            As[akq * 4 + 2][r] = pa[rr].z; As[akq * 4 + 3][r] = pa[rr].w;
        }
#pragma unroll
        for (int hh = 0; hh < 2; ++hh) {
            Bs[bkq * 8 + hh * 4 + 0][bn] = pb[hh].x; Bs[bkq * 8 + hh * 4 + 1][bn] = pb[hh].y;
            Bs[bkq * 8 + hh * 4 + 2][bn] = pb[hh].z; Bs[bkq * 8 + hh * 4 + 3][bn] = pb[hh].w;
        }
        __syncthreads();

        if (kt < 15) {
            const int kn = (kt + 1) * 32;
#pragma unroll
            for (int rr = 0; rr < 4; ++rr)
                pa[rr] = *reinterpret_cast<const float4*>(
                    &g_h[mBase + arow + rr * 32][kn + akq * 4]);
#pragma unroll
            for (int hh = 0; hh < 2; ++hh)
                pb[hh] = *reinterpret_cast<const float4*>(
                    &Wlin[(size_t)bn * (2 * H_DIM) + kn + bkq * 8 + hh * 4]);
        }

#pragma unroll 8
        for (int k = 0; k < 32; ++k) {
            float4 a0 = *reinterpret_cast<const float4*>(&As[k][ty * 8]);
            float4 a1 = *reinterpret_cast<const float4*>(&As[k][ty * 8 + 4]);
            float4 b4 = *reinterpret_cast<const float4*>(&Bs[k][tx * 4]);
            ull ap[4] = {pk2(a0.x, a0.y), pk2(a0.z, a0.w), pk2(a1.x, a1.y), pk2(a1.z, a1.w)};
            ull bd[4] = {pk2(b4.x, b4.x), pk2(b4.y, b4.y), pk2(b4.z, b4.z), pk2(b4.w, b4.w)};
#pragma unroll
            for (int m = 0; m < 4; ++m)
#pragma unroll
                for (int j = 0; j < 4; ++j)
                    acc[m][j] = fma2_(ap[m], bd[j], acc[m][j]);
        }
        __syncthreads();
    }

    const int n0 = tx * 4;
    float bias[4];
#pragma unroll
    for (int j = 0; j < 4; ++j) bias[j] = blin[n0 + j];
#pragma unroll
    for (int m = 0; m < 4; ++m) {
        float lo[4], hi[4];
#pragma unroll
        for (int j = 0; j < 4; ++j) upk2(acc[m][j], lo[j], hi[j]);
        int row0 = mBase + ty * 8 + 2 * m;
#pragma unroll
        for (int r = 0; r < 2; ++r) {
            const float* src = r ? hi : lo;
            float4 o = make_float4(src[0] + bias[0], src[1] + bias[1],
                                   src[2] + bias[2], src[3] + bias[3]);
            *reinterpret_cast<float4*>(&g_sc[row0 + r][n0]) = o;
        }
    }
}

// =====================================================================
// Kernel C: Viterbi DP + backtrace (R15 version).
// =====================================================================
__global__ void __launch_bounds__(512) kC(
    const float* __restrict__ pw,
    const float* __restrict__ startv, const float* __restrict__ stopv,
    float* __restrict__ out)
{
    __shared__ float delta[2][64];
    __shared__ float fin[64];
    __shared__ unsigned char bp[T_LEN - 1][64];

    const int b = blockIdx.x;
    const int tid = threadIdx.x;
    const int s = tid >> 3;      // state 0..63
    const int p = tid & 7;       // part 0..7

    float Pr[8];
#pragma unroll
    for (int i = 0; i < 8; ++i) Pr[i] = pw[(p * 8 + i) * 64 + s];

    if (p == 0) delta[0][s] = startv[s] + g_sc[b][s];
    __syncthreads();

    float scA = g_sc[(size_t)1 * B_SZ + b][s];
    float scB = g_sc[(size_t)2 * B_SZ + b][s];
    for (int t = 1; t < T_LEN; ++t) {
        const int pp = (t - 1) & 1, qq = t & 1;
        float4 d0 = *reinterpret_cast<const float4*>(&delta[pp][p * 8]);
        float4 d1 = *reinterpret_cast<const float4*>(&delta[pp][p * 8 + 4]);
        float dv[8] = {d0.x, d0.y, d0.z, d0.w, d1.x, d1.y, d1.z, d1.w};

        float best = dv[0] + Pr[0];
        int bi = p * 8;
#pragma unroll
        for (int i = 1; i < 8; ++i) {
            float v = dv[i] + Pr[i];
            if (v > best) { best = v; bi = p * 8 + i; }
        }
#pragma unroll
        for (int off = 1; off < 8; off <<= 1) {
            float ov = __shfl_xor_sync(0xffffffffu, best, off);
            int oi = __shfl_xor_sync(0xffffffffu, bi, off);
            if (ov > best || (ov == best && oi < bi)) { best = ov; bi = oi; }
        }

        const float sc = scA;
        scA = scB;
        if (t + 2 < T_LEN) scB = g_sc[(size_t)(t + 2) * B_SZ + b][s];

        if (p == 0) {
            bp[t - 1][s] = (unsigned char)bi;
            delta[qq][s] = best + sc;
        }
        __syncthreads();
    }

    if (p == 0) fin[s] = delta[(T_LEN - 1) & 1][s] + stopv[s];
    __syncthreads();

    if (tid == 0) {
        float best = fin[0]; int bi0 = 0;
        for (int i = 1; i < 64; ++i) if (fin[i] > best) { best = fin[i]; bi0 = i; }
        out[b] = best;
        int st = bi0;
        out[64 + (size_t)(T_LEN - 1) * B_SZ + b] = (float)st;
        for (int tt = T_LEN - 2; tt >= 0; --tt) {
            st = bp[tt][st];
            out[64 + (size_t)tt * B_SZ + b] = (float)st;
        }
    }
}

// =====================================================================
extern "C" void kernel_launch(void* const* d_in, const int* in_sizes, int n_in,
                              void* d_out, int out_size)
{
    const int*   obs  = (const int*)  d_in[0];
    const float* h0   = (const float*)d_in[1];
    const float* c0   = (const float*)d_in[2];
    const float* emb  = (const float*)d_in[3];
    const float* WihF = (const float*)d_in[4];
    const float* WhhF = (const float*)d_in[5];
    const float* bihF = (const float*)d_in[6];
    const float* bhhF = (const float*)d_in[7];
    const float* WihB = (const float*)d_in[8];
    const float* WhhB = (const float*)d_in[9];
    const float* bihB = (const float*)d_in[10];
    const float* bhhB = (const float*)d_in[11];
    const float* Wlin = (const float*)d_in[12];
    const float* blin = (const float*)d_in[13];
    const float* pw   = (const float*)d_in[14];
    const float* stv  = (const float*)d_in[15];
    const float* spv  = (const float*)d_in[16];
    float* out = (float*)d_out;

    const int smemB = (int)sizeof(SmemB);
    cudaFuncSetAttribute(kB, cudaFuncAttributeMaxDynamicSharedMemorySize, smemB);

    kZ<<<64, 1024>>>();
    kA<<<dim3(256, 32), 256>>>(obs, emb, WihF, WihB, bihF, bhhF, bihB, bhhB);
    kB<<<128, 512, smemB>>>(WhhF, WhhB, h0, c0);
    kS<<<256, 256>>>(Wlin, blin);
    kC<<<64, 512>>>(pw, stv, spv, out);
}